// round 1
// baseline (speedup 1.0000x reference)
#include <cuda_runtime.h>
#include <math.h>

#define N 4096
#define IN_F 256
#define H0 64
#define H1 64
#define H2 32
#define CAP 256
#define SLOPE 0.01f

// -------- scratch (device globals; no allocation) --------
__device__ int   g_nbr_idx[3 * N * CAP];   // sorted neighbor lists per (relation,row)
__device__ int   g_nbr_cnt[3 * N];         // true degree (row sum of 0/1 adj)
__device__ float g_Wh[3 * N * H0];
__device__ float g_ssrc[3 * N];
__device__ float g_sdst[3 * N];
__device__ float g_hr[3 * N * H0];         // per-relation attention outputs
__device__ float g_support[N * H0];
__device__ float g_support2[N * H2];
__device__ float g_resid[N * H2];

__device__ __forceinline__ float leaky(float v) { return v >= 0.f ? v : SLOPE * v; }

// ---------------- Kernel A: Wh = x @ W_r, s_src, s_dst -------------------
// grid (N, 3), 64 threads
__global__ void wh_kernel(const float* __restrict__ x,
                          const float* __restrict__ W1, const float* __restrict__ a1,
                          const float* __restrict__ W2, const float* __restrict__ a2,
                          const float* __restrict__ W3, const float* __restrict__ a3) {
    int i = blockIdx.x;
    int r = blockIdx.y;
    const float* W = (r == 0) ? W1 : (r == 1) ? W2 : W3;
    const float* a = (r == 0) ? a1 : (r == 1) ? a2 : a3;
    __shared__ float sx[IN_F];
    __shared__ float sred[H0];
    int tid = threadIdx.x;
    for (int k = tid; k < IN_F; k += 64) sx[k] = x[(size_t)i * IN_F + k];
    __syncthreads();
    float acc = 0.f;
#pragma unroll 8
    for (int k = 0; k < IN_F; k++) acc = fmaf(sx[k], W[k * H0 + tid], acc);
    g_Wh[((size_t)r * N + i) * H0 + tid] = acc;

    // s_src = Wh . a[:64]
    sred[tid] = acc * a[tid];
    __syncthreads();
    for (int off = 32; off > 0; off >>= 1) {
        if (tid < off) sred[tid] += sred[tid + off];
        __syncthreads();
    }
    if (tid == 0) g_ssrc[r * N + i] = sred[0];
    __syncthreads();
    // s_dst = Wh . a[64:]
    sred[tid] = acc * a[H0 + tid];
    __syncthreads();
    for (int off = 32; off > 0; off >>= 1) {
        if (tid < off) sred[tid] += sred[tid + off];
        __syncthreads();
    }
    if (tid == 0) g_sdst[r * N + i] = sred[0];
}

// ---------------- Kernel B: adj scan + neighbor list + softmax attention --
// grid (N, 3), 256 threads. One block scans one 16KB adj row.
__global__ void __launch_bounds__(256, 4)
attn_kernel(const float* __restrict__ adj) {
    int i = blockIdx.x;
    int r = blockIdx.y;
    int tid = threadIdx.x;
    const float* row = adj + ((size_t)r * N + i) * N;

    __shared__ int   s_idx[CAP];
    __shared__ float s_w[CAP];
    __shared__ int   s_pref[256];
    __shared__ float s_red[256];
    __shared__ float s_acc[4][H0];

    // --- deterministic sorted nonzero scan: thread t owns cols [16t, 16t+16)
    int base = tid * 16;
    int local[16];
    int c = 0;
#pragma unroll
    for (int q = 0; q < 4; q++) {
        float4 v = *reinterpret_cast<const float4*>(row + base + q * 4);
        if (v.x > 0.f) local[c++] = base + q * 4 + 0;
        if (v.y > 0.f) local[c++] = base + q * 4 + 1;
        if (v.z > 0.f) local[c++] = base + q * 4 + 2;
        if (v.w > 0.f) local[c++] = base + q * 4 + 3;
    }
    s_pref[tid] = c;
    __syncthreads();
    // inclusive Hillis-Steele scan over 256 counts
    for (int off = 1; off < 256; off <<= 1) {
        int add = (tid >= off) ? s_pref[tid - off] : 0;
        __syncthreads();
        s_pref[tid] += add;
        __syncthreads();
    }
    int total = s_pref[255];
    int start = s_pref[tid] - c;
    for (int k = 0; k < c; k++)
        if (start + k < CAP) s_idx[start + k] = local[k];
    if (tid == 0) {
        g_nbr_cnt[r * N + i] = total;
    }
    __syncthreads();
    int cnt = min(total, CAP);

    // persist list for GNN layers
    int* glst = g_nbr_idx + ((size_t)r * N + i) * CAP;
    for (int k = tid; k < cnt; k += 256) glst[k] = s_idx[k];

    // --- scores: leaky(s_src_i + s_dst_j)
    float si = g_ssrc[r * N + i];
    for (int k = tid; k < cnt; k += 256)
        s_w[k] = leaky(si + g_sdst[r * N + s_idx[k]]);
    __syncthreads();

    // --- max reduce
    float m = -3.4e38f;
    for (int k = tid; k < cnt; k += 256) m = fmaxf(m, s_w[k]);
    s_red[tid] = m;
    __syncthreads();
    for (int off = 128; off > 0; off >>= 1) {
        if (tid < off) s_red[tid] = fmaxf(s_red[tid], s_red[tid + off]);
        __syncthreads();
    }
    m = s_red[0];
    __syncthreads();

    // --- exp + sum reduce
    float sum = 0.f;
    for (int k = tid; k < cnt; k += 256) {
        float e = expf(s_w[k] - m);
        s_w[k] = e;
        sum += e;
    }
    s_red[tid] = sum;
    __syncthreads();
    for (int off = 128; off > 0; off >>= 1) {
        if (tid < off) s_red[tid] += s_red[tid + off];
        __syncthreads();
    }
    float inv = 1.f / s_red[0];
    __syncthreads();

    // --- aggregate: h_i = sum_k w_k * Wh[j_k, :] (4 k-chunks x 64 features)
    int f = tid & 63;
    int kc = tid >> 6;
    const float* WhR = g_Wh + (size_t)r * N * H0;
    float acc = 0.f;
    for (int k = kc; k < cnt; k += 4)
        acc = fmaf(s_w[k], WhR[(size_t)s_idx[k] * H0 + f], acc);
    s_acc[kc][f] = acc;
    __syncthreads();
    if (tid < H0) {
        float o = (s_acc[0][tid] + s_acc[1][tid] + s_acc[2][tid] + s_acc[3][tid]) * inv;
        g_hr[((size_t)r * N + i) * H0 + tid] = o;
    }
}

// ---------------- Kernel C: h' = sigmoid(mean of 3); support = h' @ Wg0 ---
// grid N, 64 threads
__global__ void fuse_kernel(const float* __restrict__ Wg0) {
    int i = blockIdx.x;
    int tid = threadIdx.x;
    __shared__ float hp[H0];
    float v = (g_hr[(size_t)i * H0 + tid] +
               g_hr[((size_t)N + i) * H0 + tid] +
               g_hr[((size_t)2 * N + i) * H0 + tid]) * (1.f / 3.f);
    hp[tid] = 1.f / (1.f + expf(-v));
    __syncthreads();
    float acc = 0.f;
#pragma unroll 8
    for (int k = 0; k < H0; k++) acc = fmaf(hp[k], Wg0[k * H1 + tid], acc);
    g_support[(size_t)i * H1 + tid] = acc;
}

__device__ __forceinline__ int read_relation(const void* p) {
    int r = *reinterpret_cast<const int*>(p);
    if (r < 0 || r > 2) {
        float f = *reinterpret_cast<const float*>(p);
        r = (int)f;
        if (r < 0 || r > 2) r = 0;
    }
    return r;
}

// ---------------- Kernel D: gnn layer 1 + support2 + residual proj -------
// grid N, 64 threads
__global__ void gnn1_kernel(const float* __restrict__ bg0,
                            const float* __restrict__ Wg1,
                            const float* __restrict__ Wr,
                            const float* __restrict__ br,
                            const void* __restrict__ relation) {
    int i = blockIdx.x;
    int tid = threadIdx.x;
    int r = read_relation(relation);
    int rowid = r * N + i;
    int total = g_nbr_cnt[rowid];
    int cnt = min(total, CAP);
    const int* glst = g_nbr_idx + (size_t)rowid * CAP;
    __shared__ int sl[CAP];
    __shared__ float shp[H1];
    for (int k = tid; k < cnt; k += 64) sl[k] = glst[k];
    __syncthreads();
    float agg = 0.f;
    for (int k = 0; k < cnt; k++) agg += g_support[(size_t)sl[k] * H1 + tid];
    float hp = leaky(agg * (1.f / (float)total) + bg0[tid]);
    shp[tid] = hp;
    __syncthreads();
    if (tid < H2) {
        float s2 = 0.f, rr = 0.f;
#pragma unroll 8
        for (int k = 0; k < H1; k++) {
            float h = shp[k];
            s2 = fmaf(h, Wg1[k * H2 + tid], s2);
            rr = fmaf(h, Wr[tid * H1 + k], rr);   // Wr is [H2, H1] row-major
        }
        g_support2[(size_t)i * H2 + tid] = s2;
        g_resid[(size_t)i * H2 + tid] = rr + br[tid];
    }
}

// ---------------- Kernel F: gnn layer 2 + add residual -> out -------------
// grid N, 32 threads
__global__ void gnn2_kernel(const float* __restrict__ bg1,
                            const void* __restrict__ relation,
                            float* __restrict__ out) {
    int i = blockIdx.x;
    int tid = threadIdx.x;
    int r = read_relation(relation);
    int rowid = r * N + i;
    int total = g_nbr_cnt[rowid];
    int cnt = min(total, CAP);
    const int* glst = g_nbr_idx + (size_t)rowid * CAP;
    __shared__ int sl[CAP];
    for (int k = tid; k < cnt; k += 32) sl[k] = glst[k];
    __syncthreads();
    float agg = 0.f;
    for (int k = 0; k < cnt; k++) agg += g_support2[(size_t)sl[k] * H2 + tid];
    float v = leaky(agg * (1.f / (float)total) + bg1[tid]);
    out[(size_t)i * H2 + tid] = v + g_resid[(size_t)i * H2 + tid];
}

extern "C" void kernel_launch(void* const* d_in, const int* in_sizes, int n_in,
                              void* d_out, int out_size) {
    const float* x   = (const float*)d_in[0];
    const float* adj = (const float*)d_in[1];
    const float* W1  = (const float*)d_in[2];
    const float* a1  = (const float*)d_in[3];
    const float* W2  = (const float*)d_in[4];
    const float* a2  = (const float*)d_in[5];
    const float* W3  = (const float*)d_in[6];
    const float* a3  = (const float*)d_in[7];
    const float* Wg0 = (const float*)d_in[8];
    const float* bg0 = (const float*)d_in[9];
    const float* Wg1 = (const float*)d_in[10];
    const float* bg1 = (const float*)d_in[11];
    const float* Wr  = (const float*)d_in[12];
    const float* br  = (const float*)d_in[13];
    const void*  rel = d_in[14];
    float* out = (float*)d_out;

    dim3 gridA(N, 3);
    wh_kernel<<<gridA, 64>>>(x, W1, a1, W2, a2, W3, a3);
    attn_kernel<<<gridA, 256>>>(adj);
    fuse_kernel<<<N, 64>>>(Wg0);
    gnn1_kernel<<<N, 64>>>(bg0, Wg1, Wr, br, rel);
    gnn2_kernel<<<N, 32>>>(bg1, rel, out);
}

// round 2
// speedup vs baseline: 1.2436x; 1.2436x over previous
#include <cuda_runtime.h>
#include <math.h>
#include <float.h>

#define N 4096
#define IN_F 256
#define H0 64
#define H1 64
#define H2 32
#define CAP 256
#define SLOPE 0.01f
#define TM 16

// -------- scratch (device globals; no allocation) --------
__device__ int   g_nbr_idx[3 * N * CAP];
__device__ int   g_nbr_cnt[3 * N];
__device__ float g_Wh[3 * N * H0];
__device__ float g_ssrc[3 * N];
__device__ float g_sdst[3 * N];
__device__ float g_hr[3 * N * H0];
__device__ float g_support[N * H1];
__device__ float g_support2[N * H2];
__device__ float g_resid[N * H2];

__device__ __forceinline__ float leaky(float v) { return v >= 0.f ? v : SLOPE * v; }

// ---------------- Kernel A: Wh = x @ W_r, s_src, s_dst -------------------
// grid (N/TM, 3), 256 threads. Tiled: 16 rows/block, W chunked through smem.
__global__ void __launch_bounds__(256)
wh_kernel(const float* __restrict__ x,
          const float* __restrict__ W1, const float* __restrict__ a1,
          const float* __restrict__ W2, const float* __restrict__ a2,
          const float* __restrict__ W3, const float* __restrict__ a3) {
    int r = blockIdx.y;
    const float* W = (r == 0) ? W1 : (r == 1) ? W2 : W3;
    const float* a = (r == 0) ? a1 : (r == 1) ? a2 : a3;
    int row0 = blockIdx.x * TM;
    int tid = threadIdx.x;
    int rr = tid >> 4;   // local row 0..15
    int cg = tid & 15;   // column group of 4

    __shared__ float  sx[TM][IN_F];   // 16 KB
    __shared__ float4 sW[64][16];     // 16 KB W chunk (64 k-rows x 64 cols)

    // load x tile (1024 float4, 4 per thread, coalesced)
    {
        const float4* xs = (const float4*)(x + (size_t)row0 * IN_F);
        float4* sx4 = (float4*)&sx[0][0];
#pragma unroll
        for (int q = 0; q < 4; q++) sx4[tid + q * 256] = xs[tid + q * 256];
    }

    float4 acc = make_float4(0.f, 0.f, 0.f, 0.f);
    for (int k0 = 0; k0 < IN_F; k0 += 64) {
        __syncthreads();
        const float4* Ws = (const float4*)(W + (size_t)k0 * H0);
        float4* sW4 = (float4*)&sW[0][0];
#pragma unroll
        for (int q = 0; q < 4; q++) sW4[tid + q * 256] = Ws[tid + q * 256];
        __syncthreads();
#pragma unroll 16
        for (int kk = 0; kk < 64; kk++) {
            float xv = sx[rr][k0 + kk];
            float4 w = sW[kk][cg];
            acc.x = fmaf(xv, w.x, acc.x);
            acc.y = fmaf(xv, w.y, acc.y);
            acc.z = fmaf(xv, w.z, acc.z);
            acc.w = fmaf(xv, w.w, acc.w);
        }
    }
    int grow = row0 + rr;
    *(float4*)(g_Wh + ((size_t)r * N + grow) * H0 + cg * 4) = acc;

    // s_src = Wh.a[:64], s_dst = Wh.a[64:] via shfl reduce over 16 lanes/row
    float4 as = *(const float4*)(a + cg * 4);
    float4 ad = *(const float4*)(a + H0 + cg * 4);
    float ps = acc.x * as.x + acc.y * as.y + acc.z * as.z + acc.w * as.w;
    float pd = acc.x * ad.x + acc.y * ad.y + acc.z * ad.z + acc.w * ad.w;
#pragma unroll
    for (int off = 8; off > 0; off >>= 1) {
        ps += __shfl_down_sync(0xffffffffu, ps, off, 16);
        pd += __shfl_down_sync(0xffffffffu, pd, off, 16);
    }
    if (cg == 0) { g_ssrc[r * N + grow] = ps; g_sdst[r * N + grow] = pd; }
}

// ---------------- Kernel B: adj scan + neighbor list + softmax attention --
// grid (N, 3), 256 threads. One block scans one 16KB adj row.
__global__ void __launch_bounds__(256)
attn_kernel(const float* __restrict__ adj) {
    int i = blockIdx.x;
    int r = blockIdx.y;
    int tid = threadIdx.x;
    int lane = tid & 31, wid = tid >> 5;
    const float* row = adj + ((size_t)r * N + i) * N;

    __shared__ int   s_idx[CAP];
    __shared__ float s_w[CAP];
    __shared__ int   s_wsum[8];
    __shared__ float s_m[8];
    __shared__ float s_s[8];
    __shared__ float s_acc[4][H0];

    // --- nonzero mask over 16 contiguous columns per thread
    int base = tid * 16;
    unsigned mask = 0;
#pragma unroll
    for (int q = 0; q < 4; q++) {
        float4 v = *reinterpret_cast<const float4*>(row + base + q * 4);
        if (v.x > 0.f) mask |= 1u << (q * 4 + 0);
        if (v.y > 0.f) mask |= 1u << (q * 4 + 1);
        if (v.z > 0.f) mask |= 1u << (q * 4 + 2);
        if (v.w > 0.f) mask |= 1u << (q * 4 + 3);
    }
    int c = __popc(mask);

    // --- warp-shuffle inclusive scan of counts
    int pre = c;
#pragma unroll
    for (int off = 1; off < 32; off <<= 1) {
        int nv = __shfl_up_sync(0xffffffffu, pre, off);
        if (lane >= off) pre += nv;
    }
    if (lane == 31) s_wsum[wid] = pre;
    __syncthreads();
    int wbase = 0, total = 0;
#pragma unroll
    for (int w = 0; w < 8; w++) {
        int v = s_wsum[w];
        if (w < wid) wbase += v;
        total += v;
    }
    int start = wbase + pre - c;

    // --- compact sorted indices from mask bits
    {
        unsigned mm = mask;
        int pos = start;
        while (mm) {
            int b = __ffs(mm) - 1;
            mm &= mm - 1;
            if (pos < CAP) s_idx[pos] = base + b;
            pos++;
        }
    }
    if (tid == 0) g_nbr_cnt[r * N + i] = total;
    __syncthreads();
    int cnt = min(total, CAP);

    // persist list for GNN layers
    int* glst = g_nbr_idx + ((size_t)r * N + i) * CAP;
    for (int k = tid; k < cnt; k += 256) glst[k] = s_idx[k];

    // --- score (one element per thread, cnt <= 256)
    float si = g_ssrc[r * N + i];
    float myscore = -FLT_MAX;
    if (tid < cnt) myscore = leaky(si + g_sdst[r * N + s_idx[tid]]);

    // block max: warp shuffle + 8-entry combine
    float m = myscore;
#pragma unroll
    for (int off = 16; off > 0; off >>= 1)
        m = fmaxf(m, __shfl_xor_sync(0xffffffffu, m, off));
    if (lane == 0) s_m[wid] = m;
    __syncthreads();
    float bm = s_m[0];
#pragma unroll
    for (int w = 1; w < 8; w++) bm = fmaxf(bm, s_m[w]);

    // exp + block sum
    float e = (tid < cnt) ? expf(myscore - bm) : 0.f;
    s_w[tid] = e;
    float sum = e;
#pragma unroll
    for (int off = 16; off > 0; off >>= 1)
        sum += __shfl_xor_sync(0xffffffffu, sum, off);
    if (lane == 0) s_s[wid] = sum;
    __syncthreads();
    float bs = s_s[0];
#pragma unroll
    for (int w = 1; w < 8; w++) bs += s_s[w];
    float inv = 1.f / bs;

    // --- aggregate: h_i = (sum_k w_k * Wh[j_k,:]) * inv, 4-way k-parallel
    int f = tid & 63;
    int kc = tid >> 6;
    const float* WhR = g_Wh + (size_t)r * N * H0;
    float acc = 0.f;
    for (int k = kc; k < cnt; k += 4)
        acc = fmaf(s_w[k], WhR[(size_t)s_idx[k] * H0 + f], acc);
    s_acc[kc][f] = acc;
    __syncthreads();
    if (tid < H0) {
        float o = (s_acc[0][tid] + s_acc[1][tid] + s_acc[2][tid] + s_acc[3][tid]) * inv;
        g_hr[((size_t)r * N + i) * H0 + tid] = o;
    }
}

// ---------------- Kernel C: h' = sigmoid(mean of 3); support = h' @ Wg0 ---
// grid N/4, 256 threads (4 rows per block)
__global__ void __launch_bounds__(256)
fuse_kernel(const float* __restrict__ Wg0) {
    int tid = threadIdx.x;
    int rr = tid >> 6;
    int f = tid & 63;
    int i = blockIdx.x * 4 + rr;
    __shared__ float hp[4][H0];
    float v = (g_hr[(size_t)i * H0 + f] +
               g_hr[((size_t)N + i) * H0 + f] +
               g_hr[((size_t)2 * N + i) * H0 + f]) * (1.f / 3.f);
    hp[rr][f] = 1.f / (1.f + expf(-v));
    __syncthreads();
    float acc = 0.f;
#pragma unroll 16
    for (int k = 0; k < H0; k++) acc = fmaf(hp[rr][k], Wg0[k * H1 + f], acc);
    g_support[(size_t)i * H1 + f] = acc;
}

__device__ __forceinline__ int read_relation(const void* p) {
    int r = *reinterpret_cast<const int*>(p);
    if (r < 0 || r > 2) {
        float fv = *reinterpret_cast<const float*>(p);
        r = (int)fv;
        if (r < 0 || r > 2) r = 0;
    }
    return r;
}

// ---------------- Kernel D: gnn layer 1 + support2 + residual proj -------
// grid N, 256 threads (4-way k-parallel gather)
__global__ void __launch_bounds__(256)
gnn1_kernel(const float* __restrict__ bg0,
            const float* __restrict__ Wg1,
            const float* __restrict__ Wr,
            const float* __restrict__ br,
            const void* __restrict__ relation) {
    int i = blockIdx.x;
    int tid = threadIdx.x;
    int f = tid & 63;
    int kc = tid >> 6;
    int r = read_relation(relation);
    int rowid = r * N + i;
    int total = g_nbr_cnt[rowid];
    int cnt = min(total, CAP);
    const int* glst = g_nbr_idx + (size_t)rowid * CAP;
    __shared__ int   sl[CAP];
    __shared__ float sagg[4][H1];
    __shared__ float shp[H1];
    for (int k = tid; k < cnt; k += 256) sl[k] = glst[k];
    __syncthreads();
    float acc = 0.f;
    for (int k = kc; k < cnt; k += 4)
        acc += g_support[(size_t)sl[k] * H1 + f];
    sagg[kc][f] = acc;
    __syncthreads();
    if (tid < H1) {
        float agg = sagg[0][tid] + sagg[1][tid] + sagg[2][tid] + sagg[3][tid];
        shp[tid] = leaky(agg * (1.f / (float)total) + bg0[tid]);
    }
    __syncthreads();
    if (tid < H2) {
        float s2 = 0.f;
#pragma unroll 16
        for (int k = 0; k < H1; k++) s2 = fmaf(shp[k], Wg1[k * H2 + tid], s2);
        g_support2[(size_t)i * H2 + tid] = s2;
    } else if (tid < H1) {
        int j = tid - H2;
        float rr2 = 0.f;
#pragma unroll 16
        for (int k = 0; k < H1; k++) rr2 = fmaf(shp[k], Wr[j * H1 + k], rr2);
        g_resid[(size_t)i * H2 + j] = rr2 + br[j];
    }
}

// ---------------- Kernel F: gnn layer 2 + add residual -> out -------------
// grid N, 128 threads (4-way k-parallel gather)
__global__ void __launch_bounds__(128)
gnn2_kernel(const float* __restrict__ bg1,
            const void* __restrict__ relation,
            float* __restrict__ out) {
    int i = blockIdx.x;
    int tid = threadIdx.x;
    int f = tid & 31;
    int kc = tid >> 5;
    int r = read_relation(relation);
    int rowid = r * N + i;
    int total = g_nbr_cnt[rowid];
    int cnt = min(total, CAP);
    const int* glst = g_nbr_idx + (size_t)rowid * CAP;
    __shared__ int   sl[CAP];
    __shared__ float sagg[4][H2];
    for (int k = tid; k < cnt; k += 128) sl[k] = glst[k];
    __syncthreads();
    float acc = 0.f;
    for (int k = kc; k < cnt; k += 4)
        acc += g_support2[(size_t)sl[k] * H2 + f];
    sagg[kc][f] = acc;
    __syncthreads();
    if (tid < H2) {
        float agg = sagg[0][tid] + sagg[1][tid] + sagg[2][tid] + sagg[3][tid];
        float v = leaky(agg * (1.f / (float)total) + bg1[tid]);
        out[(size_t)i * H2 + tid] = v + g_resid[(size_t)i * H2 + tid];
    }
}

extern "C" void kernel_launch(void* const* d_in, const int* in_sizes, int n_in,
                              void* d_out, int out_size) {
    const float* x   = (const float*)d_in[0];
    const float* adj = (const float*)d_in[1];
    const float* W1  = (const float*)d_in[2];
    const float* a1  = (const float*)d_in[3];
    const float* W2  = (const float*)d_in[4];
    const float* a2  = (const float*)d_in[5];
    const float* W3  = (const float*)d_in[6];
    const float* a3  = (const float*)d_in[7];
    const float* Wg0 = (const float*)d_in[8];
    const float* bg0 = (const float*)d_in[9];
    const float* Wg1 = (const float*)d_in[10];
    const float* bg1 = (const float*)d_in[11];
    const float* Wr  = (const float*)d_in[12];
    const float* br  = (const float*)d_in[13];
    const void*  rel = d_in[14];
    float* out = (float*)d_out;

    wh_kernel<<<dim3(N / TM, 3), 256>>>(x, W1, a1, W2, a2, W3, a3);
    attn_kernel<<<dim3(N, 3), 256>>>(adj);
    fuse_kernel<<<N / 4, 256>>>(Wg0);
    gnn1_kernel<<<N, 256>>>(bg0, Wg1, Wr, br, rel);
    gnn2_kernel<<<N, 128>>>(bg1, rel, out);
}

// round 3
// speedup vs baseline: 1.8517x; 1.4890x over previous
#include <cuda_runtime.h>
#include <math.h>
#include <float.h>

#define N 4096
#define IN_F 256
#define H0 64
#define H1 64
#define H2 32
#define CAP 256
#define SLOPE 0.01f
#define WH_TM 64

// -------- scratch (device globals; no allocation) --------
__device__ int   g_nbr_idx[3 * N * CAP];
__device__ int   g_nbr_cnt[3 * N];
__device__ float g_Wh[3 * N * H0];
__device__ float g_ssrc[3 * N];
__device__ float g_sdst[3 * N];
__device__ float g_hr[3 * N * H0];
__device__ float g_support[N * H1];
__device__ float g_support2[N * H2];
__device__ float g_resid[N * H2];

__device__ __forceinline__ float leaky(float v) { return v >= 0.f ? v : SLOPE * v; }

// ---------------- Kernel A: Wh = x @ W_r, s_src, s_dst -------------------
// grid (N/64, 3), 256 threads. 64x64 tile, 4x4 register tile per thread.
__global__ void __launch_bounds__(256)
wh_kernel(const float* __restrict__ x,
          const float* __restrict__ W1, const float* __restrict__ a1,
          const float* __restrict__ W2, const float* __restrict__ a2,
          const float* __restrict__ W3, const float* __restrict__ a3) {
    int r = blockIdx.y;
    const float* W = (r == 0) ? W1 : (r == 1) ? W2 : W3;
    const float* a = (r == 0) ? a1 : (r == 1) ? a2 : a3;
    int row0 = blockIdx.x * WH_TM;
    int tid = threadIdx.x;
    int rg = tid >> 4;    // row group 0..15 (4 rows each)
    int cgp = tid & 15;   // col group 0..15 (4 cols each)

    __shared__ float sx[WH_TM][64];   // 16 KB x chunk  [row][k]
    __shared__ float sW[64][64];      // 16 KB W chunk  [k][col]

    float4 acc[4];
#pragma unroll
    for (int q = 0; q < 4; q++) acc[q] = make_float4(0.f, 0.f, 0.f, 0.f);

    for (int k0 = 0; k0 < IN_F; k0 += 64) {
        __syncthreads();
        // stage x chunk: 64 rows x 64 k (1024 float4)
#pragma unroll
        for (int q = 0; q < 4; q++) {
            int lin = tid + q * 256;            // float4 index
            int rr = lin >> 4, c4 = (lin & 15) << 2;
            *(float4*)&sx[rr][c4] = *(const float4*)(x + (size_t)(row0 + rr) * IN_F + k0 + c4);
        }
        // stage W chunk: 64 k x 64 cols
#pragma unroll
        for (int q = 0; q < 4; q++) {
            int lin = tid + q * 256;
            int kr = lin >> 4, c4 = (lin & 15) << 2;
            *(float4*)&sW[kr][c4] = *(const float4*)(W + (size_t)(k0 + kr) * H0 + c4);
        }
        __syncthreads();
#pragma unroll 16
        for (int kk = 0; kk < 64; kk++) {
            float4 wv = *(float4*)&sW[kk][cgp * 4];
            float xv0 = sx[rg * 4 + 0][kk];
            float xv1 = sx[rg * 4 + 1][kk];
            float xv2 = sx[rg * 4 + 2][kk];
            float xv3 = sx[rg * 4 + 3][kk];
            acc[0].x = fmaf(xv0, wv.x, acc[0].x); acc[0].y = fmaf(xv0, wv.y, acc[0].y);
            acc[0].z = fmaf(xv0, wv.z, acc[0].z); acc[0].w = fmaf(xv0, wv.w, acc[0].w);
            acc[1].x = fmaf(xv1, wv.x, acc[1].x); acc[1].y = fmaf(xv1, wv.y, acc[1].y);
            acc[1].z = fmaf(xv1, wv.z, acc[1].z); acc[1].w = fmaf(xv1, wv.w, acc[1].w);
            acc[2].x = fmaf(xv2, wv.x, acc[2].x); acc[2].y = fmaf(xv2, wv.y, acc[2].y);
            acc[2].z = fmaf(xv2, wv.z, acc[2].z); acc[2].w = fmaf(xv2, wv.w, acc[2].w);
            acc[3].x = fmaf(xv3, wv.x, acc[3].x); acc[3].y = fmaf(xv3, wv.y, acc[3].y);
            acc[3].z = fmaf(xv3, wv.z, acc[3].z); acc[3].w = fmaf(xv3, wv.w, acc[3].w);
        }
    }

    // write Wh + compute s_src/s_dst partials
    float4 av = *(const float4*)(a + cgp * 4);
    float4 ad = *(const float4*)(a + H0 + cgp * 4);
#pragma unroll
    for (int ri = 0; ri < 4; ri++) {
        int grow = row0 + rg * 4 + ri;
        *(float4*)(g_Wh + ((size_t)r * N + grow) * H0 + cgp * 4) = acc[ri];
        float ps = acc[ri].x * av.x + acc[ri].y * av.y + acc[ri].z * av.z + acc[ri].w * av.w;
        float pd = acc[ri].x * ad.x + acc[ri].y * ad.y + acc[ri].z * ad.z + acc[ri].w * ad.w;
#pragma unroll
        for (int off = 8; off > 0; off >>= 1) {
            ps += __shfl_down_sync(0xffffffffu, ps, off, 16);
            pd += __shfl_down_sync(0xffffffffu, pd, off, 16);
        }
        if (cgp == 0) { g_ssrc[r * N + grow] = ps; g_sdst[r * N + grow] = pd; }
    }
}

// ---------------- Kernel B: adj scan + neighbor list + softmax attention --
// grid (N, 3), 256 threads. One block scans one 16KB adj row.
__global__ void __launch_bounds__(256)
attn_kernel(const float* __restrict__ adj) {
    int i = blockIdx.x;
    int r = blockIdx.y;
    int tid = threadIdx.x;
    int lane = tid & 31, wid = tid >> 5;
    const float* row = adj + ((size_t)r * N + i) * N;

    __shared__ int   s_idx[CAP];
    __shared__ float s_w[CAP];
    __shared__ int   s_wsum[8];
    __shared__ float s_m[8];
    __shared__ float s_s[8];
    __shared__ float s_acc[4][H0];

    int base = tid * 16;
    unsigned mask = 0;
#pragma unroll
    for (int q = 0; q < 4; q++) {
        float4 v = *reinterpret_cast<const float4*>(row + base + q * 4);
        if (v.x > 0.f) mask |= 1u << (q * 4 + 0);
        if (v.y > 0.f) mask |= 1u << (q * 4 + 1);
        if (v.z > 0.f) mask |= 1u << (q * 4 + 2);
        if (v.w > 0.f) mask |= 1u << (q * 4 + 3);
    }
    int c = __popc(mask);

    int pre = c;
#pragma unroll
    for (int off = 1; off < 32; off <<= 1) {
        int nv = __shfl_up_sync(0xffffffffu, pre, off);
        if (lane >= off) pre += nv;
    }
    if (lane == 31) s_wsum[wid] = pre;
    __syncthreads();
    int wbase = 0, total = 0;
#pragma unroll
    for (int w = 0; w < 8; w++) {
        int v = s_wsum[w];
        if (w < wid) wbase += v;
        total += v;
    }
    int start = wbase + pre - c;

    {
        unsigned mm = mask;
        int pos = start;
        while (mm) {
            int b = __ffs(mm) - 1;
            mm &= mm - 1;
            if (pos < CAP) s_idx[pos] = base + b;
            pos++;
        }
    }
    if (tid == 0) g_nbr_cnt[r * N + i] = total;
    __syncthreads();
    int cnt = min(total, CAP);

    int* glst = g_nbr_idx + ((size_t)r * N + i) * CAP;
    for (int k = tid; k < cnt; k += 256) glst[k] = s_idx[k];

    float si = g_ssrc[r * N + i];
    float myscore = -FLT_MAX;
    if (tid < cnt) myscore = leaky(si + g_sdst[r * N + s_idx[tid]]);

    float m = myscore;
#pragma unroll
    for (int off = 16; off > 0; off >>= 1)
        m = fmaxf(m, __shfl_xor_sync(0xffffffffu, m, off));
    if (lane == 0) s_m[wid] = m;
    __syncthreads();
    float bm = s_m[0];
#pragma unroll
    for (int w = 1; w < 8; w++) bm = fmaxf(bm, s_m[w]);

    float e = (tid < cnt) ? expf(myscore - bm) : 0.f;
    s_w[tid] = e;
    float sum = e;
#pragma unroll
    for (int off = 16; off > 0; off >>= 1)
        sum += __shfl_xor_sync(0xffffffffu, sum, off);
    if (lane == 0) s_s[wid] = sum;
    __syncthreads();
    float bs = s_s[0];
#pragma unroll
    for (int w = 1; w < 8; w++) bs += s_s[w];
    float inv = 1.f / bs;

    int f = tid & 63;
    int kc = tid >> 6;
    const float* WhR = g_Wh + (size_t)r * N * H0;
    float acc = 0.f;
    for (int k = kc; k < cnt; k += 4)
        acc = fmaf(s_w[k], WhR[(size_t)s_idx[k] * H0 + f], acc);
    s_acc[kc][f] = acc;
    __syncthreads();
    if (tid < H0) {
        float o = (s_acc[0][tid] + s_acc[1][tid] + s_acc[2][tid] + s_acc[3][tid]) * inv;
        g_hr[((size_t)r * N + i) * H0 + tid] = o;
    }
}

// ---------------- Kernel C: h' = sigmoid(mean of 3); support = h' @ Wg0 ---
__global__ void __launch_bounds__(256)
fuse_kernel(const float* __restrict__ Wg0) {
    int tid = threadIdx.x;
    int rr = tid >> 6;
    int f = tid & 63;
    int i = blockIdx.x * 4 + rr;
    __shared__ float hp[4][H0];
    float v = (g_hr[(size_t)i * H0 + f] +
               g_hr[((size_t)N + i) * H0 + f] +
               g_hr[((size_t)2 * N + i) * H0 + f]) * (1.f / 3.f);
    hp[rr][f] = 1.f / (1.f + expf(-v));
    __syncthreads();
    float acc = 0.f;
#pragma unroll 16
    for (int k = 0; k < H0; k++) acc = fmaf(hp[rr][k], Wg0[k * H1 + f], acc);
    g_support[(size_t)i * H1 + f] = acc;
}

__device__ __forceinline__ int read_relation(const void* p) {
    int r = *reinterpret_cast<const int*>(p);
    if (r < 0 || r > 2) {
        float fv = *reinterpret_cast<const float*>(p);
        r = (int)fv;
        if (r < 0 || r > 2) r = 0;
    }
    return r;
}

// ---------------- Kernel D: gnn layer 1 + support2 + residual proj -------
// grid N/8, 256 threads, warp-per-row.
__global__ void __launch_bounds__(256)
gnn1_kernel(const float* __restrict__ bg0,
            const float* __restrict__ Wg1,
            const float* __restrict__ Wr,
            const float* __restrict__ br,
            const void* __restrict__ relation) {
    int tid = threadIdx.x;
    int wid = tid >> 5, lane = tid & 31;
    int i = blockIdx.x * 8 + wid;
    int r = read_relation(relation);
    int rowid = r * N + i;

    __shared__ float sWg1[H1 * H2];        // 8 KB
    __shared__ float sWrT[H1][H2 + 1];     // 8.25 KB, transposed + padded
    __shared__ int   ssl[8][CAP];          // 8 KB
    __shared__ float shp[8][H1];           // 2 KB

    // stage weights (block-cooperative)
    for (int t = tid; t < H1 * H2; t += 256) {
        sWg1[t] = Wg1[t];
        int j = t >> 6, kk = t & 63;
        sWrT[kk][j] = Wr[t];               // Wr[j*H1+kk] with t=j*64+kk
    }

    int total = g_nbr_cnt[rowid];
    int cnt = min(total, CAP);
    const int* glst = g_nbr_idx + (size_t)rowid * CAP;
    for (int k = lane; k < cnt; k += 32) ssl[wid][k] = glst[k];
    __syncthreads();

    // gather: lane handles features (2*lane, 2*lane+1)
    const float2* sup = (const float2*)g_support;
    const int* sl = ssl[wid];
    float2 a0 = {0.f, 0.f}, a1 = {0.f, 0.f}, a2 = {0.f, 0.f}, a3 = {0.f, 0.f};
    int k = 0;
    for (; k + 4 <= cnt; k += 4) {
        int j0 = sl[k], j1 = sl[k + 1], j2 = sl[k + 2], j3 = sl[k + 3];
        float2 v0 = sup[(size_t)j0 * 32 + lane];
        float2 v1 = sup[(size_t)j1 * 32 + lane];
        float2 v2 = sup[(size_t)j2 * 32 + lane];
        float2 v3 = sup[(size_t)j3 * 32 + lane];
        a0.x += v0.x; a0.y += v0.y;
        a1.x += v1.x; a1.y += v1.y;
        a2.x += v2.x; a2.y += v2.y;
        a3.x += v3.x; a3.y += v3.y;
    }
    for (; k < cnt; k++) {
        float2 v = sup[(size_t)sl[k] * 32 + lane];
        a0.x += v.x; a0.y += v.y;
    }
    float dinv = 1.f / (float)total;
    float2 bg = ((const float2*)bg0)[lane];
    float h0 = leaky((a0.x + a1.x + a2.x + a3.x) * dinv + bg.x);
    float h1 = leaky((a0.y + a1.y + a2.y + a3.y) * dinv + bg.y);
    shp[wid][2 * lane]     = h0;
    shp[wid][2 * lane + 1] = h1;
    __syncwarp();

    // epilogue: s2[lane] and resid[lane] (H2=32 outputs each)
    float s2 = 0.f, rr2 = 0.f;
#pragma unroll 16
    for (int kk = 0; kk < H1; kk++) {
        float h = shp[wid][kk];
        s2  = fmaf(h, sWg1[kk * H2 + lane], s2);
        rr2 = fmaf(h, sWrT[kk][lane], rr2);
    }
    g_support2[(size_t)i * H2 + lane] = s2;
    g_resid[(size_t)i * H2 + lane]    = rr2 + br[lane];
}

// ---------------- Kernel F: gnn layer 2 + add residual -> out -------------
// grid N/8, 256 threads, warp-per-row.
__global__ void __launch_bounds__(256)
gnn2_kernel(const float* __restrict__ bg1,
            const void* __restrict__ relation,
            float* __restrict__ out) {
    int tid = threadIdx.x;
    int wid = tid >> 5, lane = tid & 31;
    int i = blockIdx.x * 8 + wid;
    int r = read_relation(relation);
    int rowid = r * N + i;

    __shared__ int ssl[8][CAP];

    int total = g_nbr_cnt[rowid];
    int cnt = min(total, CAP);
    const int* glst = g_nbr_idx + (size_t)rowid * CAP;
    for (int k = lane; k < cnt; k += 32) ssl[wid][k] = glst[k];
    __syncwarp();

    const float* sup2 = g_support2;
    const int* sl = ssl[wid];
    float a0 = 0.f, a1 = 0.f, a2 = 0.f, a3 = 0.f;
    int k = 0;
    for (; k + 4 <= cnt; k += 4) {
        int j0 = sl[k], j1 = sl[k + 1], j2 = sl[k + 2], j3 = sl[k + 3];
        a0 += sup2[(size_t)j0 * H2 + lane];
        a1 += sup2[(size_t)j1 * H2 + lane];
        a2 += sup2[(size_t)j2 * H2 + lane];
        a3 += sup2[(size_t)j3 * H2 + lane];
    }
    for (; k < cnt; k++) a0 += sup2[(size_t)sl[k] * H2 + lane];

    float agg = a0 + a1 + a2 + a3;
    float v = leaky(agg * (1.f / (float)total) + bg1[lane]);
    out[(size_t)i * H2 + lane] = v + g_resid[(size_t)i * H2 + lane];
}

extern "C" void kernel_launch(void* const* d_in, const int* in_sizes, int n_in,
                              void* d_out, int out_size) {
    const float* x   = (const float*)d_in[0];
    const float* adj = (const float*)d_in[1];
    const float* W1  = (const float*)d_in[2];
    const float* a1  = (const float*)d_in[3];
    const float* W2  = (const float*)d_in[4];
    const float* a2  = (const float*)d_in[5];
    const float* W3  = (const float*)d_in[6];
    const float* a3  = (const float*)d_in[7];
    const float* Wg0 = (const float*)d_in[8];
    const float* bg0 = (const float*)d_in[9];
    const float* Wg1 = (const float*)d_in[10];
    const float* bg1 = (const float*)d_in[11];
    const float* Wr  = (const float*)d_in[12];
    const float* br  = (const float*)d_in[13];
    const void*  rel = d_in[14];
    float* out = (float*)d_out;

    wh_kernel<<<dim3(N / WH_TM, 3), 256>>>(x, W1, a1, W2, a2, W3, a3);
    attn_kernel<<<dim3(N, 3), 256>>>(adj);
    fuse_kernel<<<N / 4, 256>>>(Wg0);
    gnn1_kernel<<<N / 8, 256>>>(bg0, Wg1, Wr, br, rel);
    gnn2_kernel<<<N / 8, 256>>>(bg1, rel, out);
}

// round 4
// speedup vs baseline: 2.0162x; 1.0889x over previous
#include <cuda_runtime.h>
#include <math.h>
#include <float.h>

#define N 4096
#define IN_F 256
#define H0 64
#define H1 64
#define H2 32
#define CAP 256
#define SLOPE 0.01f
#define WH_BLOCKS 192   // 64 row-tiles x 3 relations

// -------- scratch (device globals; no allocation) --------
__device__ int   g_nbr_idx[3 * N * CAP];
__device__ int   g_nbr_cnt[3 * N];
__device__ float g_Wh[3 * N * H0];
__device__ float g_ssrc[3 * N];
__device__ float g_sdst[3 * N];
__device__ float g_hr[3 * N * H0];
__device__ float g_support[N * H1];
__device__ float g_support2[N * H2];
__device__ float g_resid[N * H2];
__device__ float g_WrT[H1 * H2];   // Wr transposed to [k][j]

__device__ __forceinline__ float leaky(float v) { return v >= 0.f ? v : SLOPE * v; }

// ================= merged kernel 1: wh tiles + adj scan ===================
__device__ void wh_body(int b,
                        const float* __restrict__ x,
                        const float* __restrict__ W1, const float* __restrict__ a1,
                        const float* __restrict__ W2, const float* __restrict__ a2,
                        const float* __restrict__ W3, const float* __restrict__ a3) {
    int r = b >> 6;
    int row0 = (b & 63) * 64;
    const float* W = (r == 0) ? W1 : (r == 1) ? W2 : W3;
    const float* a = (r == 0) ? a1 : (r == 1) ? a2 : a3;
    int tid = threadIdx.x;
    int rg = tid >> 4;
    int cgp = tid & 15;

    __shared__ float sx[64][64];
    __shared__ float sW[64][64];

    float4 acc[4];
#pragma unroll
    for (int q = 0; q < 4; q++) acc[q] = make_float4(0.f, 0.f, 0.f, 0.f);

    for (int k0 = 0; k0 < IN_F; k0 += 64) {
        __syncthreads();
#pragma unroll
        for (int q = 0; q < 4; q++) {
            int lin = tid + q * 256;
            int rr = lin >> 4, c4 = (lin & 15) << 2;
            *(float4*)&sx[rr][c4] = *(const float4*)(x + (size_t)(row0 + rr) * IN_F + k0 + c4);
        }
#pragma unroll
        for (int q = 0; q < 4; q++) {
            int lin = tid + q * 256;
            int kr = lin >> 4, c4 = (lin & 15) << 2;
            *(float4*)&sW[kr][c4] = *(const float4*)(W + (size_t)(k0 + kr) * H0 + c4);
        }
        __syncthreads();
#pragma unroll 16
        for (int kk = 0; kk < 64; kk++) {
            float4 wv = *(float4*)&sW[kk][cgp * 4];
            float xv0 = sx[rg * 4 + 0][kk];
            float xv1 = sx[rg * 4 + 1][kk];
            float xv2 = sx[rg * 4 + 2][kk];
            float xv3 = sx[rg * 4 + 3][kk];
            acc[0].x = fmaf(xv0, wv.x, acc[0].x); acc[0].y = fmaf(xv0, wv.y, acc[0].y);
            acc[0].z = fmaf(xv0, wv.z, acc[0].z); acc[0].w = fmaf(xv0, wv.w, acc[0].w);
            acc[1].x = fmaf(xv1, wv.x, acc[1].x); acc[1].y = fmaf(xv1, wv.y, acc[1].y);
            acc[1].z = fmaf(xv1, wv.z, acc[1].z); acc[1].w = fmaf(xv1, wv.w, acc[1].w);
            acc[2].x = fmaf(xv2, wv.x, acc[2].x); acc[2].y = fmaf(xv2, wv.y, acc[2].y);
            acc[2].z = fmaf(xv2, wv.z, acc[2].z); acc[2].w = fmaf(xv2, wv.w, acc[2].w);
            acc[3].x = fmaf(xv3, wv.x, acc[3].x); acc[3].y = fmaf(xv3, wv.y, acc[3].y);
            acc[3].z = fmaf(xv3, wv.z, acc[3].z); acc[3].w = fmaf(xv3, wv.w, acc[3].w);
        }
    }

    float4 av = *(const float4*)(a + cgp * 4);
    float4 ad = *(const float4*)(a + H0 + cgp * 4);
#pragma unroll
    for (int ri = 0; ri < 4; ri++) {
        int grow = row0 + rg * 4 + ri;
        *(float4*)(g_Wh + ((size_t)r * N + grow) * H0 + cgp * 4) = acc[ri];
        float ps = acc[ri].x * av.x + acc[ri].y * av.y + acc[ri].z * av.z + acc[ri].w * av.w;
        float pd = acc[ri].x * ad.x + acc[ri].y * ad.y + acc[ri].z * ad.z + acc[ri].w * ad.w;
#pragma unroll
        for (int off = 8; off > 0; off >>= 1) {
            ps += __shfl_down_sync(0xffffffffu, ps, off, 16);
            pd += __shfl_down_sync(0xffffffffu, pd, off, 16);
        }
        if (cgp == 0) { g_ssrc[r * N + grow] = ps; g_sdst[r * N + grow] = pd; }
    }
}

__device__ void scan_body(int b, const float* __restrict__ adj) {
    int i = b & (N - 1);
    int r = b >> 12;
    int tid = threadIdx.x;
    int lane = tid & 31, wid = tid >> 5;
    __shared__ int s_wsum[8];

    const float4* row4 = (const float4*)(adj + ((size_t)r * N + i) * N);
    // fully coalesced: thread t loads float4 index t + q*256
    float4 v0 = row4[tid];
    float4 v1 = row4[tid + 256];
    float4 v2 = row4[tid + 512];
    float4 v3 = row4[tid + 768];
    unsigned mask = 0;
    if (v0.x > 0.f) mask |= 1u << 0;  if (v0.y > 0.f) mask |= 1u << 1;
    if (v0.z > 0.f) mask |= 1u << 2;  if (v0.w > 0.f) mask |= 1u << 3;
    if (v1.x > 0.f) mask |= 1u << 4;  if (v1.y > 0.f) mask |= 1u << 5;
    if (v1.z > 0.f) mask |= 1u << 6;  if (v1.w > 0.f) mask |= 1u << 7;
    if (v2.x > 0.f) mask |= 1u << 8;  if (v2.y > 0.f) mask |= 1u << 9;
    if (v2.z > 0.f) mask |= 1u << 10; if (v2.w > 0.f) mask |= 1u << 11;
    if (v3.x > 0.f) mask |= 1u << 12; if (v3.y > 0.f) mask |= 1u << 13;
    if (v3.z > 0.f) mask |= 1u << 14; if (v3.w > 0.f) mask |= 1u << 15;
    int c = __popc(mask);

    int pre = c;
#pragma unroll
    for (int off = 1; off < 32; off <<= 1) {
        int nv = __shfl_up_sync(0xffffffffu, pre, off);
        if (lane >= off) pre += nv;
    }
    if (lane == 31) s_wsum[wid] = pre;
    __syncthreads();
    int wbase = 0, total = 0;
#pragma unroll
    for (int w = 0; w < 8; w++) {
        int v = s_wsum[w];
        if (w < wid) wbase += v;
        total += v;
    }
    int pos = wbase + pre - c;

    int* gl = g_nbr_idx + ((size_t)(r * N + i)) * CAP;
    unsigned mm = mask;
    while (mm) {
        int bb = __ffs(mm) - 1;
        mm &= mm - 1;
        int q = bb >> 2, j = bb & 3;
        int col = ((tid + (q << 8)) << 2) + j;
        if (pos < CAP) gl[pos] = col;
        pos++;
    }
    if (tid == 0) g_nbr_cnt[r * N + i] = total;
}

__global__ void __launch_bounds__(256)
scan_wh_kernel(const float* __restrict__ x, const float* __restrict__ adj,
               const float* __restrict__ W1, const float* __restrict__ a1,
               const float* __restrict__ W2, const float* __restrict__ a2,
               const float* __restrict__ W3, const float* __restrict__ a3) {
    if (blockIdx.x < WH_BLOCKS)
        wh_body(blockIdx.x, x, W1, a1, W2, a2, W3, a3);
    else
        scan_body(blockIdx.x - WH_BLOCKS, adj);
}

// ================= kernel 2: softmax + Wh aggregation (warp per row,rel) ===
__global__ void __launch_bounds__(256)
attn2_kernel() {
    __shared__ float sw[8][CAP];
    int tid = threadIdx.x;
    int lane = tid & 31, wid = tid >> 5;
    int id = blockIdx.x * 8 + wid;     // == r*N + i
    int r = id >> 12;

    int total = g_nbr_cnt[id];
    int cnt = min(total, CAP);
    const int* gl = g_nbr_idx + (size_t)id * CAP;
    float si = g_ssrc[id];

    // pass 1: raw scores -> smem, running max
    float m = -FLT_MAX;
    for (int k = lane; k < cnt; k += 32) {
        int j = gl[k];
        float s = leaky(si + g_sdst[r * N + j]);
        sw[wid][k] = s;
        m = fmaxf(m, s);
    }
#pragma unroll
    for (int off = 16; off > 0; off >>= 1)
        m = fmaxf(m, __shfl_xor_sync(0xffffffffu, m, off));

    // pass 2: exp + sum
    float sum = 0.f;
    for (int k = lane; k < cnt; k += 32) {
        float e = expf(sw[wid][k] - m);
        sw[wid][k] = e;
        sum += e;
    }
#pragma unroll
    for (int off = 16; off > 0; off >>= 1)
        sum += __shfl_xor_sync(0xffffffffu, sum, off);
    float inv = 1.f / sum;
    __syncwarp();

    // gather: lane owns features (2lane, 2lane+1)
    const float2* Wh2 = (const float2*)g_Wh + (size_t)r * N * 32;
    float2 a0 = {0.f, 0.f}, a1 = {0.f, 0.f}, a2 = {0.f, 0.f}, a3 = {0.f, 0.f};
    for (int base = 0; base < cnt; base += 32) {
        int batch = (base + lane < cnt) ? gl[base + lane] : 0;
        int mmax = min(32, cnt - base);
        int k = 0;
        for (; k + 4 <= mmax; k += 4) {
            int j0 = __shfl_sync(0xffffffffu, batch, k + 0);
            int j1 = __shfl_sync(0xffffffffu, batch, k + 1);
            int j2 = __shfl_sync(0xffffffffu, batch, k + 2);
            int j3 = __shfl_sync(0xffffffffu, batch, k + 3);
            float w0 = sw[wid][base + k + 0];
            float w1 = sw[wid][base + k + 1];
            float w2 = sw[wid][base + k + 2];
            float w3 = sw[wid][base + k + 3];
            float2 p0 = Wh2[(size_t)j0 * 32 + lane];
            float2 p1 = Wh2[(size_t)j1 * 32 + lane];
            float2 p2 = Wh2[(size_t)j2 * 32 + lane];
            float2 p3 = Wh2[(size_t)j3 * 32 + lane];
            a0.x = fmaf(w0, p0.x, a0.x); a0.y = fmaf(w0, p0.y, a0.y);
            a1.x = fmaf(w1, p1.x, a1.x); a1.y = fmaf(w1, p1.y, a1.y);
            a2.x = fmaf(w2, p2.x, a2.x); a2.y = fmaf(w2, p2.y, a2.y);
            a3.x = fmaf(w3, p3.x, a3.x); a3.y = fmaf(w3, p3.y, a3.y);
        }
        for (; k < mmax; k++) {
            int j0 = __shfl_sync(0xffffffffu, batch, k);
            float w0 = sw[wid][base + k];
            float2 p0 = Wh2[(size_t)j0 * 32 + lane];
            a0.x = fmaf(w0, p0.x, a0.x); a0.y = fmaf(w0, p0.y, a0.y);
        }
    }
    float2 o;
    o.x = (a0.x + a1.x + a2.x + a3.x) * inv;
    o.y = (a0.y + a1.y + a2.y + a3.y) * inv;
    *(float2*)(g_hr + (size_t)id * H0 + 2 * lane) = o;
}

// ================= kernel 3: fuse + support + WrT prep =====================
__global__ void __launch_bounds__(256)
fuse_kernel(const float* __restrict__ Wg0, const float* __restrict__ Wr) {
    int tid = threadIdx.x;
    int rr = tid >> 6;
    int f = tid & 63;
    int i = blockIdx.x * 4 + rr;
    if (blockIdx.x == 0) {
#pragma unroll
        for (int t = tid; t < H1 * H2; t += 256) {
            int j = t >> 6, k = t & 63;
            g_WrT[k * H2 + j] = Wr[t];
        }
    }
    __shared__ float hp[4][H0];
    float v = (g_hr[(size_t)i * H0 + f] +
               g_hr[((size_t)N + i) * H0 + f] +
               g_hr[((size_t)2 * N + i) * H0 + f]) * (1.f / 3.f);
    hp[rr][f] = 1.f / (1.f + expf(-v));
    __syncthreads();
    float acc = 0.f;
#pragma unroll 16
    for (int k = 0; k < H0; k++) acc = fmaf(hp[rr][k], Wg0[k * H1 + f], acc);
    g_support[(size_t)i * H1 + f] = acc;
}

__device__ __forceinline__ int read_relation(const void* p) {
    int r = *reinterpret_cast<const int*>(p);
    if (r < 0 || r > 2) {
        float fv = *reinterpret_cast<const float*>(p);
        r = (int)fv;
        if (r < 0 || r > 2) r = 0;
    }
    return r;
}

// ================= kernel 4: gnn layer 1 (2 warps per row) ================
__global__ void __launch_bounds__(256)
gnn1_kernel(const float* __restrict__ bg0,
            const float* __restrict__ Wg1,
            const float* __restrict__ br,
            const void* __restrict__ relation) {
    __shared__ float sagg[4][2][H1];
    __shared__ float shp[4][H1];
    int tid = threadIdx.x;
    int lane = tid & 31, wid = tid >> 5;
    int rl = wid >> 1;
    int half = wid & 1;
    int i = blockIdx.x * 4 + rl;
    int r = read_relation(relation);
    int rowid = r * N + i;
    int total = g_nbr_cnt[rowid];
    int cnt = min(total, CAP);
    const int* gl = g_nbr_idx + (size_t)rowid * CAP;
    int m0 = (cnt + 1) >> 1;
    int kbeg = half ? m0 : 0;
    int kend = half ? cnt : m0;

    const float2* sup = (const float2*)g_support;
    float2 a0 = {0.f, 0.f}, a1 = {0.f, 0.f}, a2 = {0.f, 0.f}, a3 = {0.f, 0.f};
    for (int base = kbeg; base < kend; base += 32) {
        int batch = (base + lane < kend) ? gl[base + lane] : 0;
        int mmax = min(32, kend - base);
        int k = 0;
        for (; k + 4 <= mmax; k += 4) {
            int j0 = __shfl_sync(0xffffffffu, batch, k + 0);
            int j1 = __shfl_sync(0xffffffffu, batch, k + 1);
            int j2 = __shfl_sync(0xffffffffu, batch, k + 2);
            int j3 = __shfl_sync(0xffffffffu, batch, k + 3);
            float2 p0 = sup[(size_t)j0 * 32 + lane];
            float2 p1 = sup[(size_t)j1 * 32 + lane];
            float2 p2 = sup[(size_t)j2 * 32 + lane];
            float2 p3 = sup[(size_t)j3 * 32 + lane];
            a0.x += p0.x; a0.y += p0.y;
            a1.x += p1.x; a1.y += p1.y;
            a2.x += p2.x; a2.y += p2.y;
            a3.x += p3.x; a3.y += p3.y;
        }
        for (; k < mmax; k++) {
            int j0 = __shfl_sync(0xffffffffu, batch, k);
            float2 p0 = sup[(size_t)j0 * 32 + lane];
            a0.x += p0.x; a0.y += p0.y;
        }
    }
    float2 partial;
    partial.x = a0.x + a1.x + a2.x + a3.x;
    partial.y = a0.y + a1.y + a2.y + a3.y;
    *(float2*)&sagg[rl][half][2 * lane] = partial;
    __syncthreads();
    if (half == 0) {
        float dinv = 1.f / (float)total;
        float2 bg = ((const float2*)bg0)[lane];
        float2 p0 = *(float2*)&sagg[rl][0][2 * lane];
        float2 p1 = *(float2*)&sagg[rl][1][2 * lane];
        shp[rl][2 * lane]     = leaky((p0.x + p1.x) * dinv + bg.x);
        shp[rl][2 * lane + 1] = leaky((p0.y + p1.y) * dinv + bg.y);
    }
    __syncthreads();
    const float* Wsel = half ? (const float*)g_WrT : Wg1;   // both [k][j] (H1 x H2)
    float acc = 0.f;
#pragma unroll 16
    for (int k = 0; k < H1; k++)
        acc = fmaf(shp[rl][k], Wsel[k * H2 + lane], acc);
    if (half == 0)
        g_support2[(size_t)i * H2 + lane] = acc;
    else
        g_resid[(size_t)i * H2 + lane] = acc + br[lane];
}

// ================= kernel 5: gnn layer 2 + residual -> out ================
__global__ void __launch_bounds__(256)
gnn2_kernel(const float* __restrict__ bg1,
            const void* __restrict__ relation,
            float* __restrict__ out) {
    int tid = threadIdx.x;
    int lane = tid & 31, wid = tid >> 5;
    int i = blockIdx.x * 8 + wid;
    int r = read_relation(relation);
    int rowid = r * N + i;
    int total = g_nbr_cnt[rowid];
    int cnt = min(total, CAP);
    const int* gl = g_nbr_idx + (size_t)rowid * CAP;

    const float* sup2 = g_support2;
    float a0 = 0.f, a1 = 0.f, a2 = 0.f, a3 = 0.f;
    for (int base = 0; base < cnt; base += 32) {
        int batch = (base + lane < cnt) ? gl[base + lane] : 0;
        int mmax = min(32, cnt - base);
        int k = 0;
        for (; k + 4 <= mmax; k += 4) {
            int j0 = __shfl_sync(0xffffffffu, batch, k + 0);
            int j1 = __shfl_sync(0xffffffffu, batch, k + 1);
            int j2 = __shfl_sync(0xffffffffu, batch, k + 2);
            int j3 = __shfl_sync(0xffffffffu, batch, k + 3);
            a0 += sup2[(size_t)j0 * H2 + lane];
            a1 += sup2[(size_t)j1 * H2 + lane];
            a2 += sup2[(size_t)j2 * H2 + lane];
            a3 += sup2[(size_t)j3 * H2 + lane];
        }
        for (; k < mmax; k++) {
            int j0 = __shfl_sync(0xffffffffu, batch, k);
            a0 += sup2[(size_t)j0 * H2 + lane];
        }
    }
    float agg = a0 + a1 + a2 + a3;
    float v = leaky(agg * (1.f / (float)total) + bg1[lane]);
    out[(size_t)i * H2 + lane] = v + g_resid[(size_t)i * H2 + lane];
}

extern "C" void kernel_launch(void* const* d_in, const int* in_sizes, int n_in,
                              void* d_out, int out_size) {
    const float* x   = (const float*)d_in[0];
    const float* adj = (const float*)d_in[1];
    const float* W1  = (const float*)d_in[2];
    const float* a1  = (const float*)d_in[3];
    const float* W2  = (const float*)d_in[4];
    const float* a2  = (const float*)d_in[5];
    const float* W3  = (const float*)d_in[6];
    const float* a3  = (const float*)d_in[7];
    const float* Wg0 = (const float*)d_in[8];
    const float* bg0 = (const float*)d_in[9];
    const float* Wg1 = (const float*)d_in[10];
    const float* bg1 = (const float*)d_in[11];
    const float* Wr  = (const float*)d_in[12];
    const float* br  = (const float*)d_in[13];
    const void*  rel = d_in[14];
    float* out = (float*)d_out;

    scan_wh_kernel<<<WH_BLOCKS + 3 * N, 256>>>(x, adj, W1, a1, W2, a2, W3, a3);
    attn2_kernel<<<3 * N / 8, 256>>>();
    fuse_kernel<<<N / 4, 256>>>(Wg0, Wr);
    gnn1_kernel<<<N / 4, 256>>>(bg0, Wg1, br, rel);
    gnn2_kernel<<<N / 8, 256>>>(bg1, rel, out);
}